// round 6
// baseline (speedup 1.0000x reference)
#include <cuda_runtime.h>
#include <cuda_bf16.h>

#define NMAX 100000
#define EMAX 1600000
#define F 32
#define NG 64
#define NPB 256

// ---------------- scratch (static device globals; no allocs) ----------------
__device__ int      d_row[EMAX];
__device__ int      d_col[EMAX];
__device__ float    d_nrm[EMAX];
__device__ float    d_deg[NMAX];
__device__ float    d_t1[NMAX * F];   // Tx1 = prop(x)
__device__ float    d_p2[NMAX * F];   // P2  = prop(Tx1)  (Tx2 = 2*P2 - x, folded into weights)
__device__ unsigned d_pool[NG * F];   // segment-max accumulator, order-preserving uint encoding
__device__ float    d_h1[NG * 1024];
__device__ float    d_h2[NG * 512];

// order-preserving float<->uint encoding for atomicMax
__device__ __forceinline__ unsigned fenc(float f) {
    unsigned b = __float_as_uint(f);
    return (b & 0x80000000u) ? ~b : (b | 0x80000000u);
}
__device__ __forceinline__ float fdec(unsigned u) {
    return __uint_as_float((u & 0x80000000u) ? (u & 0x7FFFFFFFu) : ~u);
}

// ---------------- kernels ----------------

__global__ void k_init(int n) {
    int i = blockIdx.x * blockDim.x + threadIdx.x;
    int nf = n * F;
    if (i < nf) { d_t1[i] = 0.f; d_p2[i] = 0.f; }
    if (i < n)  d_deg[i] = 0.f;
    if (i < NG * F) d_pool[i] = 0x007FFFFFu;  // fenc(-inf)
}

// edge_index is int32 (JAX x64 disabled coerces int64 -> int32)
__global__ void k_edgeprep(const int* __restrict__ ei, int E) {
    int e = blockIdx.x * blockDim.x + threadIdx.x;
    if (e >= E) return;
    int r = ei[e];
    int c = ei[E + e];
    d_row[e] = r;
    d_col[e] = c;
    atomicAdd(&d_deg[r], 1.0f);
}

__global__ void k_norm(int E) {
    int e = blockIdx.x * blockDim.x + threadIdx.x;
    if (e >= E) return;
    float dr = d_deg[d_row[e]];
    float dc = d_deg[d_col[e]];
    float fr = (dr > 0.f) ? rsqrtf(dr) : 0.f;
    float fc = (dc > 0.f) ? rsqrtf(dc) : 0.f;
    d_nrm[e] = -(fr * fc);
}

// scatter-add propagation: dst[col] += nrm * src[row]; warp per edge, lane = feature
__global__ void k_prop(const float* __restrict__ src, float* __restrict__ dst, int E) {
    int t = blockIdx.x * blockDim.x + threadIdx.x;
    int e = t >> 5;
    int lane = t & 31;
    if (e >= E) return;
    int r = d_row[e];
    int c = d_col[e];
    float nv = d_nrm[e];
    float v = __ldg(&src[r * F + lane]);
    atomicAdd(&dst[c * F + lane], nv * v);   // result unused -> REDG
}

// fused Chebyshev combine + per-graph max pool.
// h = x@(W0-W2) + Tx1@W1 + P2@(2*W2) + b ; pooled via running max (batch sorted)
__global__ void __launch_bounds__(256) k_combine(
    const float* __restrict__ x,
    const int* __restrict__ batch,   // int32
    const float* __restrict__ Wc,    // [3,32,32]
    const float* __restrict__ bc,    // [32]
    int n)
{
    int lane = threadIdx.x & 31;
    int warp = threadIdx.x >> 5;

    // register-resident weight columns (column = this lane's output feature)
    float w0r[32], w1r[32], w2r[32];
#pragma unroll
    for (int i = 0; i < 32; i++) {
        float a = __ldg(&Wc[i * 32 + lane]);           // W_cheb[0]
        float b = __ldg(&Wc[1024 + i * 32 + lane]);    // W_cheb[1]
        float c = __ldg(&Wc[2048 + i * 32 + lane]);    // W_cheb[2]
        w0r[i] = a - c;
        w1r[i] = b;
        w2r[i] = 2.f * c;
    }
    float bias = __ldg(&bc[lane]);

    int n0 = blockIdx.x * NPB;
    int n1 = min(n0 + NPB, n);

    float runmax = __int_as_float(0xff800000);  // -inf
    int curg = -1;

    for (int nn = n0 + warp; nn < n1; nn += 8) {
        float xv  = x[nn * F + lane];
        float t1v = d_t1[nn * F + lane];
        float p2v = d_p2[nn * F + lane];
        float acc = bias;
#pragma unroll
        for (int i = 0; i < 32; i++) {
            acc = fmaf(__shfl_sync(0xffffffffu, xv,  i), w0r[i], acc);
            acc = fmaf(__shfl_sync(0xffffffffu, t1v, i), w1r[i], acc);
            acc = fmaf(__shfl_sync(0xffffffffu, p2v, i), w2r[i], acc);
        }
        int gb = batch[nn];   // uniform across warp for a given nn, in [0, NG)
        if (gb != curg) {
            if (curg >= 0) atomicMax(&d_pool[curg * F + lane], fenc(runmax));
            curg = gb;
            runmax = acc;
        } else {
            runmax = fmaxf(runmax, acc);
        }
    }
    if (curg >= 0) atomicMax(&d_pool[curg * F + lane], fenc(runmax));
}

// h1 = relu(g @ W1 + b1) ; g decoded from pool. 64x1024 outputs, dot-32 each.
__global__ void k_mlp1(const float* __restrict__ W1, const float* __restrict__ b1) {
    int t = blockIdx.x * blockDim.x + threadIdx.x;  // 65536
    int b = t >> 10;
    int o = t & 1023;
    float acc = __ldg(&b1[o]);
#pragma unroll
    for (int i = 0; i < 32; i++) {
        float g = fdec(d_pool[b * 32 + i]);
        acc = fmaf(g, __ldg(&W1[i * 1024 + o]), acc);
    }
    d_h1[t] = fmaxf(acc, 0.f);
}

// h2 = relu(h1 @ W2 + b2): 64x512x1024 smem-tiled. 64 blocks x 8 cols.
__global__ void k_mlp2(const float* __restrict__ W2, const float* __restrict__ b2) {
    __shared__ float h1s[64 * 129];
    __shared__ float w2s[128 * 8];
    int t = threadIdx.x;
    int o0 = blockIdx.x * 8;
    int b = t >> 2;
    int jo = t & 3;
    float a0 = 0.f, a1 = 0.f;

    for (int kt = 0; kt < 1024; kt += 128) {
        for (int l = t; l < 64 * 128; l += 256) {
            int r = l >> 7, c = l & 127;
            h1s[r * 129 + c] = d_h1[r * 1024 + kt + c];
        }
        for (int l = t; l < 1024; l += 256) {
            int k = l >> 3, j = l & 7;
            w2s[l] = __ldg(&W2[(kt + k) * 512 + o0 + j]);
        }
        __syncthreads();
#pragma unroll
        for (int k = 0; k < 128; k++) {
            float h = h1s[b * 129 + k];
            a0 = fmaf(h, w2s[k * 8 + jo], a0);
            a1 = fmaf(h, w2s[k * 8 + jo + 4], a1);
        }
        __syncthreads();
    }
    d_h2[b * 512 + o0 + jo]     = fmaxf(a0 + __ldg(&b2[o0 + jo]), 0.f);
    d_h2[b * 512 + o0 + jo + 4] = fmaxf(a1 + __ldg(&b2[o0 + jo + 4]), 0.f);
}

// out = h2 @ W3 + b3 : 256 outputs, warp per output with warp-reduce over K=512
__global__ void k_mlp3(const float* __restrict__ W3, const float* __restrict__ b3,
                       float* __restrict__ out) {
    int w = blockIdx.x * (blockDim.x >> 5) + (threadIdx.x >> 5);
    int lane = threadIdx.x & 31;
    if (w >= 256) return;
    int b = w >> 2;
    int o = w & 3;
    float s = 0.f;
    for (int k = lane; k < 512; k += 32)
        s = fmaf(d_h2[b * 512 + k], __ldg(&W3[k * 4 + o]), s);
#pragma unroll
    for (int off = 16; off; off >>= 1)
        s += __shfl_xor_sync(0xffffffffu, s, off);
    if (lane == 0) out[b * 4 + o] = s + __ldg(&b3[o]);
}

// ---------------- launch ----------------
extern "C" void kernel_launch(void* const* d_in, const int* in_sizes, int n_in,
                              void* d_out, int out_size) {
    const float* x     = (const float*)d_in[0];
    const int*   ei    = (const int*)d_in[1];     // int32 (JAX default x64 off)
    const int*   batch = (const int*)d_in[2];     // int32
    const float* Wc    = (const float*)d_in[3];
    const float* bc    = (const float*)d_in[4];
    const float* W1    = (const float*)d_in[5];
    const float* b1    = (const float*)d_in[6];
    const float* W2    = (const float*)d_in[7];
    const float* b2    = (const float*)d_in[8];
    const float* W3    = (const float*)d_in[9];
    const float* b3    = (const float*)d_in[10];

    int N = in_sizes[0] / F;
    int E = in_sizes[1] / 2;

    void *t1p = nullptr, *p2p = nullptr;
    cudaGetSymbolAddress(&t1p, d_t1);
    cudaGetSymbolAddress(&p2p, d_p2);

    int nf = N * F;
    k_init<<<(nf + 255) / 256, 256>>>(N);
    k_edgeprep<<<(E + 255) / 256, 256>>>(ei, E);
    k_norm<<<(E + 255) / 256, 256>>>(E);

    long long pth = (long long)E * 32;
    int pblocks = (int)((pth + 255) / 256);
    k_prop<<<pblocks, 256>>>(x, (float*)t1p, E);
    k_prop<<<pblocks, 256>>>((const float*)t1p, (float*)p2p, E);

    k_combine<<<(N + NPB - 1) / NPB, 256>>>(x, batch, Wc, bc, N);

    k_mlp1<<<256, 256>>>(W1, b1);
    k_mlp2<<<64, 256>>>(W2, b2);
    k_mlp3<<<32, 256>>>(W3, b3, (float*)d_out);
}

// round 9
// speedup vs baseline: 1.5136x; 1.5136x over previous
#include <cuda_runtime.h>
#include <cuda_bf16.h>

#define NMAX 100000
#define EMAX 1600000
#define F 32
#define NG 64
#define NPB 256
#define SCANB 1024

// ---------------- scratch (static device globals; no allocs) ----------------
__device__ int      d_row[EMAX];
__device__ int      d_col[EMAX];
__device__ int2     d_epack[EMAX];     // CSR-ordered (src_row, nrm-as-int)
__device__ int      d_degr[NMAX];      // out-degree (segment_sum over row)
__device__ int      d_cnt[NMAX];       // in-count per col (CSR sizes)
__device__ int      d_ptr[NMAX + 1];   // CSR offsets
__device__ int      d_fill[NMAX];      // running fill pointers
__device__ int      d_bsum[128];
__device__ int      d_boff[128];
__device__ float    d_t1[NMAX * F];    // Tx1 = prop(x)
__device__ float    d_p2[NMAX * F];    // P2  = prop(Tx1)
__device__ unsigned d_pool[NG * F];    // segment-max, order-preserving uint encoding
__device__ float    d_h1[NG * 1024];
__device__ float    d_h2[NG * 512];

__device__ __forceinline__ unsigned fenc(float f) {
    unsigned b = __float_as_uint(f);
    return (b & 0x80000000u) ? ~b : (b | 0x80000000u);
}
__device__ __forceinline__ float fdec(unsigned u) {
    return __uint_as_float((u & 0x80000000u) ? (u & 0x7FFFFFFFu) : ~u);
}

// ---------------- kernels ----------------

__global__ void k_init(int n) {
    int i = blockIdx.x * blockDim.x + threadIdx.x;
    if (i < n) { d_degr[i] = 0; d_cnt[i] = 0; }
    if (i < NG * F) d_pool[i] = 0x007FFFFFu;  // fenc(-inf)
}

// edge_index is int32. Count row-degree and col-incount, stash indices.
__global__ void k_count(const int* __restrict__ ei, int E) {
    int e = blockIdx.x * blockDim.x + threadIdx.x;
    if (e >= E) return;
    int r = ei[e];
    int c = ei[E + e];
    d_row[e] = r;
    d_col[e] = c;
    atomicAdd(&d_degr[r], 1);
    atomicAdd(&d_cnt[c], 1);
}

// exclusive prefix scan of d_cnt -> d_ptr (3-phase)
__global__ void k_scan1(int n) {
    __shared__ int s[SCANB];
    int i = blockIdx.x * SCANB + threadIdx.x;
    int v = (i < n) ? d_cnt[i] : 0;
    s[threadIdx.x] = v;
    __syncthreads();
#pragma unroll
    for (int off = 1; off < SCANB; off <<= 1) {
        int t = (threadIdx.x >= off) ? s[threadIdx.x - off] : 0;
        __syncthreads();
        s[threadIdx.x] += t;
        __syncthreads();
    }
    if (i < n) d_ptr[i] = s[threadIdx.x] - v;  // exclusive
    if (threadIdx.x == SCANB - 1) d_bsum[blockIdx.x] = s[SCANB - 1];
}

__global__ void k_scan2(int nb) {
    if (threadIdx.x == 0) {
        int acc = 0;
        for (int i = 0; i < nb; i++) { int v = d_bsum[i]; d_boff[i] = acc; acc += v; }
    }
}

__global__ void k_scan3(int n, int E) {
    int i = blockIdx.x * SCANB + threadIdx.x;
    if (i < n) {
        int p = d_ptr[i] + d_boff[blockIdx.x];
        d_ptr[i] = p;
        d_fill[i] = p;
    }
    if (i == 0) d_ptr[n] = E;
}

// scatter edges into CSR slots, computing nrm on the fly
__global__ void k_scatter(int E) {
    int e = blockIdx.x * blockDim.x + threadIdx.x;
    if (e >= E) return;
    int r = d_row[e];
    int c = d_col[e];
    int dr = d_degr[r];
    int dc = d_degr[c];
    float fr = (dr > 0) ? rsqrtf((float)dr) : 0.f;
    float fc = (dc > 0) ? rsqrtf((float)dc) : 0.f;
    float nrm = -(fr * fc);
    int p = atomicAdd(&d_fill[c], 1);
    d_epack[p] = make_int2(r, __float_as_int(nrm));
}

// gather propagation: dst[c] = sum_{e in CSR[c]} nrm_e * src[row_e]; warp/node
__global__ void __launch_bounds__(256) k_gather(const float* __restrict__ src,
                                                float* __restrict__ dst, int n) {
    int w = (blockIdx.x * blockDim.x + threadIdx.x) >> 5;
    int lane = threadIdx.x & 31;
    if (w >= n) return;
    int p = d_ptr[w];
    int pe = d_ptr[w + 1];
    float acc = 0.f;
    // unroll-by-4: batch independent index loads, then 4 gather lines in flight
    for (; p + 4 <= pe; p += 4) {
        int2 e0 = d_epack[p];
        int2 e1 = d_epack[p + 1];
        int2 e2 = d_epack[p + 2];
        int2 e3 = d_epack[p + 3];
        float v0 = __ldg(&src[e0.x * F + lane]);
        float v1 = __ldg(&src[e1.x * F + lane]);
        float v2 = __ldg(&src[e2.x * F + lane]);
        float v3 = __ldg(&src[e3.x * F + lane]);
        acc = fmaf(__int_as_float(e0.y), v0, acc);
        acc = fmaf(__int_as_float(e1.y), v1, acc);
        acc = fmaf(__int_as_float(e2.y), v2, acc);
        acc = fmaf(__int_as_float(e3.y), v3, acc);
    }
    for (; p < pe; p++) {
        int2 e = d_epack[p];
        acc = fmaf(__int_as_float(e.y), __ldg(&src[e.x * F + lane]), acc);
    }
    dst[w * F + lane] = acc;
}

// fused Chebyshev combine + per-graph max pool.
// h = x@(W0-W2) + Tx1@W1 + P2@(2*W2) + b ; pooled via running max (batch sorted)
__global__ void __launch_bounds__(256) k_combine(
    const float* __restrict__ x,
    const int* __restrict__ batch,
    const float* __restrict__ Wc,
    const float* __restrict__ bc,
    int n)
{
    int lane = threadIdx.x & 31;
    int warp = threadIdx.x >> 5;

    float w0r[32], w1r[32], w2r[32];
#pragma unroll
    for (int i = 0; i < 32; i++) {
        float a = __ldg(&Wc[i * 32 + lane]);
        float b = __ldg(&Wc[1024 + i * 32 + lane]);
        float c = __ldg(&Wc[2048 + i * 32 + lane]);
        w0r[i] = a - c;
        w1r[i] = b;
        w2r[i] = 2.f * c;
    }
    float bias = __ldg(&bc[lane]);

    int n0 = blockIdx.x * NPB;
    int n1 = min(n0 + NPB, n);

    float runmax = __int_as_float(0xff800000);
    int curg = -1;

    for (int nn = n0 + warp; nn < n1; nn += 8) {
        float xv  = x[nn * F + lane];
        float t1v = d_t1[nn * F + lane];
        float p2v = d_p2[nn * F + lane];
        float acc = bias;
#pragma unroll
        for (int i = 0; i < 32; i++) {
            acc = fmaf(__shfl_sync(0xffffffffu, xv,  i), w0r[i], acc);
            acc = fmaf(__shfl_sync(0xffffffffu, t1v, i), w1r[i], acc);
            acc = fmaf(__shfl_sync(0xffffffffu, p2v, i), w2r[i], acc);
        }
        int gb = batch[nn];
        if (gb != curg) {
            if (curg >= 0) atomicMax(&d_pool[curg * F + lane], fenc(runmax));
            curg = gb;
            runmax = acc;
        } else {
            runmax = fmaxf(runmax, acc);
        }
    }
    if (curg >= 0) atomicMax(&d_pool[curg * F + lane], fenc(runmax));
}

__global__ void k_mlp1(const float* __restrict__ W1, const float* __restrict__ b1) {
    int t = blockIdx.x * blockDim.x + threadIdx.x;
    int b = t >> 10;
    int o = t & 1023;
    float acc = __ldg(&b1[o]);
#pragma unroll
    for (int i = 0; i < 32; i++) {
        float g = fdec(d_pool[b * 32 + i]);
        acc = fmaf(g, __ldg(&W1[i * 1024 + o]), acc);
    }
    d_h1[t] = fmaxf(acc, 0.f);
}

__global__ void k_mlp2(const float* __restrict__ W2, const float* __restrict__ b2) {
    __shared__ float h1s[64 * 129];
    __shared__ float w2s[128 * 8];
    int t = threadIdx.x;
    int o0 = blockIdx.x * 8;
    int b = t >> 2;
    int jo = t & 3;
    float a0 = 0.f, a1 = 0.f;

    for (int kt = 0; kt < 1024; kt += 128) {
        for (int l = t; l < 64 * 128; l += 256) {
            int r = l >> 7, c = l & 127;
            h1s[r * 129 + c] = d_h1[r * 1024 + kt + c];
        }
        for (int l = t; l < 1024; l += 256) {
            int k = l >> 3, j = l & 7;
            w2s[l] = __ldg(&W2[(kt + k) * 512 + o0 + j]);
        }
        __syncthreads();
#pragma unroll
        for (int k = 0; k < 128; k++) {
            float h = h1s[b * 129 + k];
            a0 = fmaf(h, w2s[k * 8 + jo], a0);
            a1 = fmaf(h, w2s[k * 8 + jo + 4], a1);
        }
        __syncthreads();
    }
    d_h2[b * 512 + o0 + jo]     = fmaxf(a0 + __ldg(&b2[o0 + jo]), 0.f);
    d_h2[b * 512 + o0 + jo + 4] = fmaxf(a1 + __ldg(&b2[o0 + jo + 4]), 0.f);
}

__global__ void k_mlp3(const float* __restrict__ W3, const float* __restrict__ b3,
                       float* __restrict__ out) {
    int w = blockIdx.x * (blockDim.x >> 5) + (threadIdx.x >> 5);
    int lane = threadIdx.x & 31;
    if (w >= 256) return;
    int b = w >> 2;
    int o = w & 3;
    float s = 0.f;
    for (int k = lane; k < 512; k += 32)
        s = fmaf(d_h2[b * 512 + k], __ldg(&W3[k * 4 + o]), s);
#pragma unroll
    for (int off = 16; off; off >>= 1)
        s += __shfl_xor_sync(0xffffffffu, s, off);
    if (lane == 0) out[b * 4 + o] = s + __ldg(&b3[o]);
}

// ---------------- launch ----------------
extern "C" void kernel_launch(void* const* d_in, const int* in_sizes, int n_in,
                              void* d_out, int out_size) {
    const float* x     = (const float*)d_in[0];
    const int*   ei    = (const int*)d_in[1];
    const int*   batch = (const int*)d_in[2];
    const float* Wc    = (const float*)d_in[3];
    const float* bc    = (const float*)d_in[4];
    const float* W1    = (const float*)d_in[5];
    const float* b1    = (const float*)d_in[6];
    const float* W2    = (const float*)d_in[7];
    const float* b2    = (const float*)d_in[8];
    const float* W3    = (const float*)d_in[9];
    const float* b3    = (const float*)d_in[10];

    int N = in_sizes[0] / F;
    int E = in_sizes[1] / 2;

    void *t1p = nullptr, *p2p = nullptr;
    cudaGetSymbolAddress(&t1p, d_t1);
    cudaGetSymbolAddress(&p2p, d_p2);

    int nblk_scan = (N + SCANB - 1) / SCANB;   // 98 for N=100000

    k_init<<<(N + 255) / 256, 256>>>(N);
    k_count<<<(E + 255) / 256, 256>>>(ei, E);
    k_scan1<<<nblk_scan, SCANB>>>(N);
    k_scan2<<<1, 32>>>(nblk_scan);
    k_scan3<<<nblk_scan, SCANB>>>(N, E);
    k_scatter<<<(E + 255) / 256, 256>>>(E);

    int gth_blocks = (N * 32 + 255) / 256;
    k_gather<<<gth_blocks, 256>>>(x, (float*)t1p, N);
    k_gather<<<gth_blocks, 256>>>((const float*)t1p, (float*)p2p, N);

    k_combine<<<(N + NPB - 1) / NPB, 256>>>(x, batch, Wc, bc, N);

    k_mlp1<<<256, 256>>>(W1, b1);
    k_mlp2<<<64, 256>>>(W2, b2);
    k_mlp3<<<32, 256>>>(W3, b3, (float*)d_out);
}